// round 5
// baseline (speedup 1.0000x reference)
#include <cuda_runtime.h>

#define BB 8
#define LL 2048
#define HH 8
#define EE 64
#define MM 64
#define LHALF 1024
#define NCHUNK 8

typedef unsigned long long ull;

// Scratch (device globals — no allocation allowed). 16B-aligned for vector ops.
__device__ __align__(16) ull g_twc[LL];                        // (cos, cos) of 2πk/2048
__device__ __align__(16) ull g_tws[LL];                        // (-sin, -sin)
__device__ __align__(16) ull g_Xpr[NCHUNK][BB*HH*MM*EE/2];     // fwd partial Re: [c][bh][m][i/2]
__device__ __align__(16) ull g_Xpi[NCHUNK][BB*HH*MM*EE/2];     // fwd partial Im
__device__ __align__(16) float g_Yr[BB*HH*MM*EE];              // modes Re: [bh][m][o]
__device__ __align__(16) float g_Yi[BB*HH*MM*EE];              // modes Im
__device__ __align__(16) float g_Wtr[HH*MM*EE*EE];             // w_real: [h][m][i][o]
__device__ __align__(16) float g_Wti[HH*MM*EE*EE];             // w_imag: [h][m][i][o]

__device__ __forceinline__ ull fma2(ull a, ull b, ull c) {
    ull d;
    asm("fma.rn.f32x2 %0, %1, %2, %3;" : "=l"(d) : "l"(a), "l"(b), "l"(c));
    return d;
}
__device__ __forceinline__ ull add2(ull a, ull b) {
    ull d;
    asm("add.rn.f32x2 %0, %1, %2;" : "=l"(d) : "l"(a), "l"(b));
    return d;
}
__device__ __forceinline__ ull pack2(float x, float y) {
    ull r; asm("mov.b64 %0, {%1, %2};" : "=l"(r) : "f"(x), "f"(y)); return r;
}
__device__ __forceinline__ float2 unpack2(ull v) {
    float2 r; asm("mov.b64 {%0, %1}, %2;" : "=f"(r.x), "=f"(r.y) : "l"(v)); return r;
}

// ---------------------------------------------------------------------------
// Duplicated twiddle tables: g_twc[k]=(c,c), g_tws[k]=(-s,-s), θ=2πk/2048.
// ---------------------------------------------------------------------------
__global__ void k_tw() {
    int k = blockIdx.x * blockDim.x + threadIdx.x;
    if (k < LL) {
        float s, c;
        sincospif((float)k * (1.0f / 1024.0f), &s, &c);
        g_twc[k] = pack2(c, c);
        g_tws[k] = pack2(-s, -s);
    }
}

// ---------------------------------------------------------------------------
// W transpose: [h][i][o][m] -> [h][m][i][o]  (coalesced both sides via smem)
// ---------------------------------------------------------------------------
__global__ void __launch_bounds__(256) k_trans(const float* __restrict__ wre,
                                               const float* __restrict__ wim) {
    __shared__ float t[EE][EE + 1];
    const int h = blockIdx.x >> 6;
    const int i = blockIdx.x & 63;
    const int tid = threadIdx.x;
    const size_t in_base = (size_t)blockIdx.x * (EE * MM);
    const size_t out_base = (size_t)h * (MM * EE * EE) + (size_t)i * EE;

    for (int idx = tid; idx < EE * MM; idx += 256) t[idx >> 6][idx & 63] = wre[in_base + idx];
    __syncthreads();
    for (int idx = tid; idx < MM * EE; idx += 256) {
        const int m = idx >> 6, o = idx & 63;
        g_Wtr[out_base + (size_t)m * (EE * EE) + o] = t[o][m];
    }
    __syncthreads();
    for (int idx = tid; idx < EE * MM; idx += 256) t[idx >> 6][idx & 63] = wim[in_base + idx];
    __syncthreads();
    for (int idx = tid; idx < MM * EE; idx += 256) {
        const int m = idx >> 6, o = idx & 63;
        g_Wti[out_base + (size_t)m * (EE * EE) + o] = t[o][m];
    }
}

// ---------------------------------------------------------------------------
// Forward truncated DFT, radix-2 fold, i-vectorized:
//   Xr(i,i+1) += u(i,i+1)*(c,c) ; Xi(i,i+1) += u(i,i+1)*(-s,-s)
// Grid (bh=64, lchunk=8). Block 128. Thread tile: 8 i x 4 m (full m in block).
// ---------------------------------------------------------------------------
__global__ void __launch_bounds__(128) k_fwd(const float* __restrict__ x) {
    __shared__ __align__(16) ull   s_twc[LL];      // 16 KB
    __shared__ __align__(16) ull   s_tws[LL];      // 16 KB
    __shared__ __align__(16) float s_u[32][EE];    // 8 KB
    __shared__ __align__(16) float s_v[32][EE];    // 8 KB
    const int tid = threadIdx.x;
    const int bh = blockIdx.x;
    const int b = bh >> 3, h = bh & 7;
    const int c = blockIdx.y;

    for (int i = tid; i < LL; i += 128) { s_twc[i] = g_twc[i]; s_tws[i] = g_tws[i]; }

    const int i0 = (tid & 7) * 8;
    const int m0 = (tid >> 3) * 4;   // 0..60, multiple of 4 -> parity(m0+j)=j&1

    ull aR[4][4], aI[4][4];
    #pragma unroll
    for (int j = 0; j < 4; ++j)
        #pragma unroll
        for (int k = 0; k < 4; ++k) { aR[j][k] = 0ull; aI[j][k] = 0ull; }

    const float* xb = x + ((size_t)b * LL * HH + h) * EE;

    for (int stage = 0; stage < 4; ++stage) {
        const int lbase = c * 128 + stage * 32;
        __syncthreads();
        for (int idx4 = tid; idx4 < 32 * 16; idx4 += 128) {
            const int sl = idx4 >> 4;
            const int ii = (idx4 & 15) * 4;
            const float4 a = *(const float4*)&xb[(size_t)(lbase + sl) * (HH * EE) + ii];
            const float4 d = *(const float4*)&xb[(size_t)(lbase + sl + LHALF) * (HH * EE) + ii];
            *(float4*)&s_u[sl][ii] = make_float4(a.x + d.x, a.y + d.y, a.z + d.z, a.w + d.w);
            *(float4*)&s_v[sl][ii] = make_float4(a.x - d.x, a.y - d.y, a.z - d.z, a.w - d.w);
        }
        __syncthreads();
        #pragma unroll 2
        for (int sl = 0; sl < 32; ++sl) {
            const int l = lbase + sl;
            // adjacent-i pairs come pre-packed from shared memory
            const ulonglong2 U0 = *(const ulonglong2*)&s_u[sl][i0];
            const ulonglong2 U1 = *(const ulonglong2*)&s_u[sl][i0 + 4];
            const ulonglong2 V0 = *(const ulonglong2*)&s_v[sl][i0];
            const ulonglong2 V1 = *(const ulonglong2*)&s_v[sl][i0 + 4];
            #pragma unroll
            for (int j = 0; j < 4; ++j) {
                const int idx = ((m0 + j) * l) & (LL - 1);
                const ull cc = s_twc[idx];
                const ull ss = s_tws[idx];
                if (j & 1) {
                    aR[j][0] = fma2(V0.x, cc, aR[j][0]); aI[j][0] = fma2(V0.x, ss, aI[j][0]);
                    aR[j][1] = fma2(V0.y, cc, aR[j][1]); aI[j][1] = fma2(V0.y, ss, aI[j][1]);
                    aR[j][2] = fma2(V1.x, cc, aR[j][2]); aI[j][2] = fma2(V1.x, ss, aI[j][2]);
                    aR[j][3] = fma2(V1.y, cc, aR[j][3]); aI[j][3] = fma2(V1.y, ss, aI[j][3]);
                } else {
                    aR[j][0] = fma2(U0.x, cc, aR[j][0]); aI[j][0] = fma2(U0.x, ss, aI[j][0]);
                    aR[j][1] = fma2(U0.y, cc, aR[j][1]); aI[j][1] = fma2(U0.y, ss, aI[j][1]);
                    aR[j][2] = fma2(U1.x, cc, aR[j][2]); aI[j][2] = fma2(U1.x, ss, aI[j][2]);
                    aR[j][3] = fma2(U1.y, cc, aR[j][3]); aI[j][3] = fma2(U1.y, ss, aI[j][3]);
                }
            }
        }
    }

    #pragma unroll
    for (int j = 0; j < 4; ++j) {
        const size_t base = ((size_t)bh * MM + (m0 + j)) * (EE / 2) + (i0 >> 1);
        ull* pr = &g_Xpr[c][base];
        ull* pi = &g_Xpi[c][base];
        pr[0] = aR[j][0]; pr[1] = aR[j][1]; pr[2] = aR[j][2]; pr[3] = aR[j][3];
        pi[0] = aI[j][0]; pi[1] = aI[j][1]; pi[2] = aI[j][2]; pi[3] = aI[j][3];
    }
}

// ---------------------------------------------------------------------------
// Mode mixing per (m,h): reduce NCHUNK partials, complex GEMM over i, fold
// irfft scale (m==0?1:2)/L. Writes separated Re/Im for k_inv.
// ---------------------------------------------------------------------------
__global__ void __launch_bounds__(128) k_mix() {
    __shared__ __align__(16) float sXr[BB][EE], sXi[BB][EE];
    __shared__ __align__(16) float sWr[EE][EE], sWi[EE][EE];
    const int m = blockIdx.x, h = blockIdx.y;
    const int tid = threadIdx.x;

    for (int idx = tid; idx < BB * EE / 2; idx += 128) {
        const int b = idx >> 5, ip = idx & 31;
        float xr0 = 0.f, xr1 = 0.f, xi0 = 0.f, xi1 = 0.f;
        const size_t offp = (((size_t)(b * HH + h)) * MM + m) * (EE / 2) + ip;
        #pragma unroll
        for (int cc = 0; cc < NCHUNK; ++cc) {
            const float2 r = unpack2(g_Xpr[cc][offp]);
            const float2 i2 = unpack2(g_Xpi[cc][offp]);
            xr0 += r.x; xr1 += r.y; xi0 += i2.x; xi1 += i2.y;
        }
        sXr[b][2 * ip] = xr0; sXr[b][2 * ip + 1] = xr1;
        sXi[b][2 * ip] = xi0; sXi[b][2 * ip + 1] = xi1;
    }
    const size_t wbase = ((size_t)h * MM + m) * (EE * EE);
    for (int idx = tid; idx < EE * EE; idx += 128) {
        sWr[idx >> 6][idx & 63] = g_Wtr[wbase + idx];
        sWi[idx >> 6][idx & 63] = g_Wti[wbase + idx];
    }
    __syncthreads();

    const int b = tid >> 4;
    const int o0 = (tid & 15) * 4;
    float ar0 = 0, ar1 = 0, ar2 = 0, ar3 = 0;
    float ai0 = 0, ai1 = 0, ai2 = 0, ai3 = 0;
    #pragma unroll 4
    for (int i = 0; i < EE; ++i) {
        const float xr = sXr[b][i], xi = sXi[b][i];
        const float4 w_r = *(const float4*)&sWr[i][o0];
        const float4 w_i = *(const float4*)&sWi[i][o0];
        ar0 = fmaf(xr, w_r.x, ar0); ar0 = fmaf(-xi, w_i.x, ar0);
        ai0 = fmaf(xr, w_i.x, ai0); ai0 = fmaf( xi, w_r.x, ai0);
        ar1 = fmaf(xr, w_r.y, ar1); ar1 = fmaf(-xi, w_i.y, ar1);
        ai1 = fmaf(xr, w_i.y, ai1); ai1 = fmaf( xi, w_r.y, ai1);
        ar2 = fmaf(xr, w_r.z, ar2); ar2 = fmaf(-xi, w_i.z, ar2);
        ai2 = fmaf(xr, w_i.z, ai2); ai2 = fmaf( xi, w_r.z, ai2);
        ar3 = fmaf(xr, w_r.w, ar3); ar3 = fmaf(-xi, w_i.w, ar3);
        ai3 = fmaf(xr, w_i.w, ai3); ai3 = fmaf( xi, w_r.w, ai3);
    }
    const float sc = (m == 0 ? 1.0f : 2.0f) * (1.0f / (float)LL);
    const size_t dst = (((size_t)(b * HH + h)) * MM + m) * EE + o0;
    *(float4*)&g_Yr[dst] = make_float4(ar0 * sc, ar1 * sc, ar2 * sc, ar3 * sc);
    *(float4*)&g_Yi[dst] = make_float4(ai0 * sc, ai1 * sc, ai2 * sc, ai3 * sc);
}

// ---------------------------------------------------------------------------
// Inverse truncated DFT, radix-2 fold, o-vectorized:
//   acc(o,o+1) += Yr(o,o+1)*(c,c) + Yi(o,o+1)*(-s,-s)
//   y_l = E+O, y_{l+1024} = E-O
// Grid (bh=64, lchunk=8, ohalf=2). Block 128. Thread: 2 l x 8 o, 2 passes.
// ---------------------------------------------------------------------------
__global__ void __launch_bounds__(128) k_inv(float* __restrict__ y) {
    __shared__ __align__(16) ull   s_twc[LL];       // 16 KB
    __shared__ __align__(16) ull   s_tws[LL];       // 16 KB
    __shared__ __align__(16) float s_Yr[MM * 32];   // 8 KB  [m][o-half]
    __shared__ __align__(16) float s_Yi[MM * 32];   // 8 KB
    const int tid = threadIdx.x;
    const int bh = blockIdx.x;
    const int b = bh >> 3, h = bh & 7;
    const int lc = blockIdx.y;
    const int oh = blockIdx.z;

    for (int i = tid; i < LL; i += 128) { s_twc[i] = g_twc[i]; s_tws[i] = g_tws[i]; }
    {
        const size_t src = (size_t)bh * (MM * EE) + oh * 32;
        for (int idx = tid; idx < MM * 32; idx += 128) {
            const int m = idx >> 5, o = idx & 31;
            s_Yr[idx] = g_Yr[src + (size_t)m * EE + o];
            s_Yi[idx] = g_Yi[src + (size_t)m * EE + o];
        }
    }
    __syncthreads();

    const int o0 = (tid & 3) * 8;     // local in half
    const int lg = tid >> 2;          // 0..31
    const int o_g = oh * 32 + o0;
    float* yb = y + ((size_t)b * LL * HH + h) * EE + o_g;
    const ull m1 = pack2(-1.0f, -1.0f);

    for (int pass = 0; pass < 2; ++pass) {
        const int lA = lc * 128 + pass * 64 + lg * 2;
        const int lB = lA + 1;

        ull aeA[4], aoA[4], aeB[4], aoB[4];
        #pragma unroll
        for (int k = 0; k < 4; ++k) { aeA[k] = 0; aoA[k] = 0; aeB[k] = 0; aoB[k] = 0; }

        int iA = 0, iB = 0;   // (m*lA)&2047, (m*lB)&2047 for even m
        #pragma unroll 4
        for (int m = 0; m < MM; m += 2) {
            {   // even m
                const ull cA = s_twc[iA], sA = s_tws[iA];
                const ull cB = s_twc[iB], sB = s_tws[iB];
                const ulonglong2 R0 = *(const ulonglong2*)&s_Yr[m * 32 + o0];
                const ulonglong2 R1 = *(const ulonglong2*)&s_Yr[m * 32 + o0 + 4];
                const ulonglong2 I0 = *(const ulonglong2*)&s_Yi[m * 32 + o0];
                const ulonglong2 I1 = *(const ulonglong2*)&s_Yi[m * 32 + o0 + 4];
                aeA[0] = fma2(R0.x, cA, aeA[0]); aeA[0] = fma2(I0.x, sA, aeA[0]);
                aeA[1] = fma2(R0.y, cA, aeA[1]); aeA[1] = fma2(I0.y, sA, aeA[1]);
                aeA[2] = fma2(R1.x, cA, aeA[2]); aeA[2] = fma2(I1.x, sA, aeA[2]);
                aeA[3] = fma2(R1.y, cA, aeA[3]); aeA[3] = fma2(I1.y, sA, aeA[3]);
                aeB[0] = fma2(R0.x, cB, aeB[0]); aeB[0] = fma2(I0.x, sB, aeB[0]);
                aeB[1] = fma2(R0.y, cB, aeB[1]); aeB[1] = fma2(I0.y, sB, aeB[1]);
                aeB[2] = fma2(R1.x, cB, aeB[2]); aeB[2] = fma2(I1.x, sB, aeB[2]);
                aeB[3] = fma2(R1.y, cB, aeB[3]); aeB[3] = fma2(I1.y, sB, aeB[3]);
            }
            {   // odd m+1
                const int jA = (iA + lA) & (LL - 1);
                const int jB = (iB + lB) & (LL - 1);
                const ull cA = s_twc[jA], sA = s_tws[jA];
                const ull cB = s_twc[jB], sB = s_tws[jB];
                const ulonglong2 R0 = *(const ulonglong2*)&s_Yr[(m + 1) * 32 + o0];
                const ulonglong2 R1 = *(const ulonglong2*)&s_Yr[(m + 1) * 32 + o0 + 4];
                const ulonglong2 I0 = *(const ulonglong2*)&s_Yi[(m + 1) * 32 + o0];
                const ulonglong2 I1 = *(const ulonglong2*)&s_Yi[(m + 1) * 32 + o0 + 4];
                aoA[0] = fma2(R0.x, cA, aoA[0]); aoA[0] = fma2(I0.x, sA, aoA[0]);
                aoA[1] = fma2(R0.y, cA, aoA[1]); aoA[1] = fma2(I0.y, sA, aoA[1]);
                aoA[2] = fma2(R1.x, cA, aoA[2]); aoA[2] = fma2(I1.x, sA, aoA[2]);
                aoA[3] = fma2(R1.y, cA, aoA[3]); aoA[3] = fma2(I1.y, sA, aoA[3]);
                aoB[0] = fma2(R0.x, cB, aoB[0]); aoB[0] = fma2(I0.x, sB, aoB[0]);
                aoB[1] = fma2(R0.y, cB, aoB[1]); aoB[1] = fma2(I0.y, sB, aoB[1]);
                aoB[2] = fma2(R1.x, cB, aoB[2]); aoB[2] = fma2(I1.x, sB, aoB[2]);
                aoB[3] = fma2(R1.y, cB, aoB[3]); aoB[3] = fma2(I1.y, sB, aoB[3]);
            }
            iA = (iA + 2 * lA) & (LL - 1);
            iB = (iB + 2 * lB) & (LL - 1);
        }

        // y_l = E+O ; y_{l+1024} = E-O   (packed f32x2 add / fused sub)
        {
            ulonglong2 lo0, lo1, hi0, hi1;
            lo0.x = add2(aeA[0], aoA[0]); lo0.y = add2(aeA[1], aoA[1]);
            lo1.x = add2(aeA[2], aoA[2]); lo1.y = add2(aeA[3], aoA[3]);
            hi0.x = fma2(aoA[0], m1, aeA[0]); hi0.y = fma2(aoA[1], m1, aeA[1]);
            hi1.x = fma2(aoA[2], m1, aeA[2]); hi1.y = fma2(aoA[3], m1, aeA[3]);
            *(ulonglong2*)&yb[(size_t)lA * (HH * EE)]               = lo0;
            *(ulonglong2*)&yb[(size_t)lA * (HH * EE) + 4]           = lo1;
            *(ulonglong2*)&yb[(size_t)(lA + LHALF) * (HH * EE)]     = hi0;
            *(ulonglong2*)&yb[(size_t)(lA + LHALF) * (HH * EE) + 4] = hi1;
        }
        {
            ulonglong2 lo0, lo1, hi0, hi1;
            lo0.x = add2(aeB[0], aoB[0]); lo0.y = add2(aeB[1], aoB[1]);
            lo1.x = add2(aeB[2], aoB[2]); lo1.y = add2(aeB[3], aoB[3]);
            hi0.x = fma2(aoB[0], m1, aeB[0]); hi0.y = fma2(aoB[1], m1, aeB[1]);
            hi1.x = fma2(aoB[2], m1, aeB[2]); hi1.y = fma2(aoB[3], m1, aeB[3]);
            *(ulonglong2*)&yb[(size_t)lB * (HH * EE)]               = lo0;
            *(ulonglong2*)&yb[(size_t)lB * (HH * EE) + 4]           = lo1;
            *(ulonglong2*)&yb[(size_t)(lB + LHALF) * (HH * EE)]     = hi0;
            *(ulonglong2*)&yb[(size_t)(lB + LHALF) * (HH * EE) + 4] = hi1;
        }
    }
}

extern "C" void kernel_launch(void* const* d_in, const int* in_sizes, int n_in,
                              void* d_out, int out_size) {
    (void)in_sizes; (void)n_in; (void)out_size;
    const float* x   = (const float*)d_in[0];
    const float* wre = (const float*)d_in[1];
    const float* wim = (const float*)d_in[2];
    float* y = (float*)d_out;

    k_tw<<<2, 1024>>>();
    k_trans<<<512, 256>>>(wre, wim);
    k_fwd<<<dim3(64, 8), 128>>>(x);
    k_mix<<<dim3(MM, HH), 128>>>();
    k_inv<<<dim3(64, 8, 2), 128>>>(y);
}

// round 6
// speedup vs baseline: 1.0085x; 1.0085x over previous
#include <cuda_runtime.h>

#define BB 8
#define LL 2048
#define HH 8
#define EE 64
#define MM 64
#define LHALF 1024
#define NCHUNK 8

typedef unsigned long long ull;

// Scratch (device globals — no allocation allowed). 16B-aligned for vector ops.
// Single duplicated-cosine twiddle table: g_twd[k] = (cos(2πk/2048), cos(...)).
// -sin(2πk/2048) = cos(2π(k+512)/2048), so one table serves both factors.
__device__ __align__(16) ull g_twd[LL];
__device__ __align__(16) ull g_Xpr[NCHUNK][BB*HH*MM*EE/2];     // fwd partial Re: [c][bh][m][i/2]
__device__ __align__(16) ull g_Xpi[NCHUNK][BB*HH*MM*EE/2];     // fwd partial Im
__device__ __align__(16) float g_Yr[BB*HH*MM*EE];              // modes Re: [bh][m][o]
__device__ __align__(16) float g_Yi[BB*HH*MM*EE];              // modes Im
__device__ __align__(16) float g_Wtr[HH*MM*EE*EE];             // w_real: [h][m][i][o]
__device__ __align__(16) float g_Wti[HH*MM*EE*EE];             // w_imag: [h][m][i][o]

__device__ __forceinline__ ull fma2(ull a, ull b, ull c) {
    ull d;
    asm("fma.rn.f32x2 %0, %1, %2, %3;" : "=l"(d) : "l"(a), "l"(b), "l"(c));
    return d;
}
__device__ __forceinline__ ull add2(ull a, ull b) {
    ull d;
    asm("add.rn.f32x2 %0, %1, %2;" : "=l"(d) : "l"(a), "l"(b));
    return d;
}
__device__ __forceinline__ ull pack2(float x, float y) {
    ull r; asm("mov.b64 %0, {%1, %2};" : "=l"(r) : "f"(x), "f"(y)); return r;
}
__device__ __forceinline__ float2 unpack2(ull v) {
    float2 r; asm("mov.b64 {%0, %1}, %2;" : "=f"(r.x), "=f"(r.y) : "l"(v)); return r;
}

// ---------------------------------------------------------------------------
// Twiddle table: g_twd[k] = (cos(2πk/2048), cos(2πk/2048))
// ---------------------------------------------------------------------------
__global__ void k_tw() {
    int k = blockIdx.x * blockDim.x + threadIdx.x;
    if (k < LL) {
        float c = cospif((float)k * (1.0f / 1024.0f));
        g_twd[k] = pack2(c, c);
    }
}

// ---------------------------------------------------------------------------
// W transpose: [h][i][o][m] -> [h][m][i][o]  (coalesced both sides via smem)
// ---------------------------------------------------------------------------
__global__ void __launch_bounds__(256) k_trans(const float* __restrict__ wre,
                                               const float* __restrict__ wim) {
    __shared__ float t[EE][EE + 1];
    const int h = blockIdx.x >> 6;
    const int i = blockIdx.x & 63;
    const int tid = threadIdx.x;
    const size_t in_base = (size_t)blockIdx.x * (EE * MM);
    const size_t out_base = (size_t)h * (MM * EE * EE) + (size_t)i * EE;

    for (int idx = tid; idx < EE * MM; idx += 256) t[idx >> 6][idx & 63] = wre[in_base + idx];
    __syncthreads();
    for (int idx = tid; idx < MM * EE; idx += 256) {
        const int m = idx >> 6, o = idx & 63;
        g_Wtr[out_base + (size_t)m * (EE * EE) + o] = t[o][m];
    }
    __syncthreads();
    for (int idx = tid; idx < EE * MM; idx += 256) t[idx >> 6][idx & 63] = wim[in_base + idx];
    __syncthreads();
    for (int idx = tid; idx < MM * EE; idx += 256) {
        const int m = idx >> 6, o = idx & 63;
        g_Wti[out_base + (size_t)m * (EE * EE) + o] = t[o][m];
    }
}

// ---------------------------------------------------------------------------
// Forward truncated DFT, radix-2 fold, i-vectorized:
//   Xr(i,i+1) += u(i,i+1)*(c,c) ; Xi(i,i+1) += u(i,i+1)*(-s,-s)
// Grid (bh=64, lchunk=8). Block 128. Thread tile: 8 i x 4 m. 32 KB smem.
// ---------------------------------------------------------------------------
__global__ void __launch_bounds__(128) k_fwd(const float* __restrict__ x) {
    __shared__ __align__(16) ull   s_twd[LL];      // 16 KB (dup-cos)
    __shared__ __align__(16) float s_u[32][EE];    // 8 KB
    __shared__ __align__(16) float s_v[32][EE];    // 8 KB
    const int tid = threadIdx.x;
    const int bh = blockIdx.x;
    const int b = bh >> 3, h = bh & 7;
    const int c = blockIdx.y;

    for (int i = tid; i < LL; i += 128) s_twd[i] = g_twd[i];

    const int i0 = (tid & 7) * 8;
    const int m0 = (tid >> 3) * 4;   // 0..60, multiple of 4 -> parity(m0+j)=j&1

    ull aR[4][4], aI[4][4];
    #pragma unroll
    for (int j = 0; j < 4; ++j)
        #pragma unroll
        for (int k = 0; k < 4; ++k) { aR[j][k] = 0ull; aI[j][k] = 0ull; }

    const float* xb = x + ((size_t)b * LL * HH + h) * EE;

    for (int stage = 0; stage < 4; ++stage) {
        const int lbase = c * 128 + stage * 32;
        __syncthreads();
        for (int idx4 = tid; idx4 < 32 * 16; idx4 += 128) {
            const int sl = idx4 >> 4;
            const int ii = (idx4 & 15) * 4;
            const float4 a = *(const float4*)&xb[(size_t)(lbase + sl) * (HH * EE) + ii];
            const float4 d = *(const float4*)&xb[(size_t)(lbase + sl + LHALF) * (HH * EE) + ii];
            *(float4*)&s_u[sl][ii] = make_float4(a.x + d.x, a.y + d.y, a.z + d.z, a.w + d.w);
            *(float4*)&s_v[sl][ii] = make_float4(a.x - d.x, a.y - d.y, a.z - d.z, a.w - d.w);
        }
        __syncthreads();
        #pragma unroll 2
        for (int sl = 0; sl < 32; ++sl) {
            const int l = lbase + sl;
            // adjacent-i pairs come pre-packed from shared memory
            const ulonglong2 U0 = *(const ulonglong2*)&s_u[sl][i0];
            const ulonglong2 U1 = *(const ulonglong2*)&s_u[sl][i0 + 4];
            const ulonglong2 V0 = *(const ulonglong2*)&s_v[sl][i0];
            const ulonglong2 V1 = *(const ulonglong2*)&s_v[sl][i0 + 4];
            #pragma unroll
            for (int j = 0; j < 4; ++j) {
                const int idx = ((m0 + j) * l) & (LL - 1);
                const ull cc = s_twd[idx];
                const ull ss = s_twd[(idx + 512) & (LL - 1)];   // (-sin,-sin)
                if (j & 1) {
                    aR[j][0] = fma2(V0.x, cc, aR[j][0]); aI[j][0] = fma2(V0.x, ss, aI[j][0]);
                    aR[j][1] = fma2(V0.y, cc, aR[j][1]); aI[j][1] = fma2(V0.y, ss, aI[j][1]);
                    aR[j][2] = fma2(V1.x, cc, aR[j][2]); aI[j][2] = fma2(V1.x, ss, aI[j][2]);
                    aR[j][3] = fma2(V1.y, cc, aR[j][3]); aI[j][3] = fma2(V1.y, ss, aI[j][3]);
                } else {
                    aR[j][0] = fma2(U0.x, cc, aR[j][0]); aI[j][0] = fma2(U0.x, ss, aI[j][0]);
                    aR[j][1] = fma2(U0.y, cc, aR[j][1]); aI[j][1] = fma2(U0.y, ss, aI[j][1]);
                    aR[j][2] = fma2(U1.x, cc, aR[j][2]); aI[j][2] = fma2(U1.x, ss, aI[j][2]);
                    aR[j][3] = fma2(U1.y, cc, aR[j][3]); aI[j][3] = fma2(U1.y, ss, aI[j][3]);
                }
            }
        }
    }

    #pragma unroll
    for (int j = 0; j < 4; ++j) {
        const size_t base = ((size_t)bh * MM + (m0 + j)) * (EE / 2) + (i0 >> 1);
        ull* pr = &g_Xpr[c][base];
        ull* pi = &g_Xpi[c][base];
        pr[0] = aR[j][0]; pr[1] = aR[j][1]; pr[2] = aR[j][2]; pr[3] = aR[j][3];
        pi[0] = aI[j][0]; pi[1] = aI[j][1]; pi[2] = aI[j][2]; pi[3] = aI[j][3];
    }
}

// ---------------------------------------------------------------------------
// Mode mixing per (m,h): reduce NCHUNK partials, complex GEMM over i, fold
// irfft scale (m==0?1:2)/L. Writes separated Re/Im for k_inv.
// ---------------------------------------------------------------------------
__global__ void __launch_bounds__(128) k_mix() {
    __shared__ __align__(16) float sXr[BB][EE], sXi[BB][EE];
    __shared__ __align__(16) float sWr[EE][EE], sWi[EE][EE];
    const int m = blockIdx.x, h = blockIdx.y;
    const int tid = threadIdx.x;

    for (int idx = tid; idx < BB * EE / 2; idx += 128) {
        const int b = idx >> 5, ip = idx & 31;
        float xr0 = 0.f, xr1 = 0.f, xi0 = 0.f, xi1 = 0.f;
        const size_t offp = (((size_t)(b * HH + h)) * MM + m) * (EE / 2) + ip;
        #pragma unroll
        for (int cc = 0; cc < NCHUNK; ++cc) {
            const float2 r = unpack2(g_Xpr[cc][offp]);
            const float2 i2 = unpack2(g_Xpi[cc][offp]);
            xr0 += r.x; xr1 += r.y; xi0 += i2.x; xi1 += i2.y;
        }
        sXr[b][2 * ip] = xr0; sXr[b][2 * ip + 1] = xr1;
        sXi[b][2 * ip] = xi0; sXi[b][2 * ip + 1] = xi1;
    }
    const size_t wbase = ((size_t)h * MM + m) * (EE * EE);
    for (int idx = tid; idx < EE * EE; idx += 128) {
        sWr[idx >> 6][idx & 63] = g_Wtr[wbase + idx];
        sWi[idx >> 6][idx & 63] = g_Wti[wbase + idx];
    }
    __syncthreads();

    const int b = tid >> 4;
    const int o0 = (tid & 15) * 4;
    float ar0 = 0, ar1 = 0, ar2 = 0, ar3 = 0;
    float ai0 = 0, ai1 = 0, ai2 = 0, ai3 = 0;
    #pragma unroll 4
    for (int i = 0; i < EE; ++i) {
        const float xr = sXr[b][i], xi = sXi[b][i];
        const float4 w_r = *(const float4*)&sWr[i][o0];
        const float4 w_i = *(const float4*)&sWi[i][o0];
        ar0 = fmaf(xr, w_r.x, ar0); ar0 = fmaf(-xi, w_i.x, ar0);
        ai0 = fmaf(xr, w_i.x, ai0); ai0 = fmaf( xi, w_r.x, ai0);
        ar1 = fmaf(xr, w_r.y, ar1); ar1 = fmaf(-xi, w_i.y, ar1);
        ai1 = fmaf(xr, w_i.y, ai1); ai1 = fmaf( xi, w_r.y, ai1);
        ar2 = fmaf(xr, w_r.z, ar2); ar2 = fmaf(-xi, w_i.z, ar2);
        ai2 = fmaf(xr, w_i.z, ai2); ai2 = fmaf( xi, w_r.z, ai2);
        ar3 = fmaf(xr, w_r.w, ar3); ar3 = fmaf(-xi, w_i.w, ar3);
        ai3 = fmaf(xr, w_i.w, ai3); ai3 = fmaf( xi, w_r.w, ai3);
    }
    const float sc = (m == 0 ? 1.0f : 2.0f) * (1.0f / (float)LL);
    const size_t dst = (((size_t)(b * HH + h)) * MM + m) * EE + o0;
    *(float4*)&g_Yr[dst] = make_float4(ar0 * sc, ar1 * sc, ar2 * sc, ar3 * sc);
    *(float4*)&g_Yi[dst] = make_float4(ai0 * sc, ai1 * sc, ai2 * sc, ai3 * sc);
}

// ---------------------------------------------------------------------------
// Inverse truncated DFT, radix-2 fold, o-vectorized:
//   acc(o,o+1) += Yr(o,o+1)*(c,c) + Yi(o,o+1)*(-s,-s)
//   y_l = E+O, y_{l+1024} = E-O
// Grid (bh=64, lchunk=8, ohalf=2). Block 128. 32 KB smem.
// ---------------------------------------------------------------------------
__global__ void __launch_bounds__(128) k_inv(float* __restrict__ y) {
    __shared__ __align__(16) ull   s_twd[LL];       // 16 KB (dup-cos)
    __shared__ __align__(16) float s_Yr[MM * 32];   // 8 KB  [m][o-half]
    __shared__ __align__(16) float s_Yi[MM * 32];   // 8 KB
    const int tid = threadIdx.x;
    const int bh = blockIdx.x;
    const int b = bh >> 3, h = bh & 7;
    const int lc = blockIdx.y;
    const int oh = blockIdx.z;

    for (int i = tid; i < LL; i += 128) s_twd[i] = g_twd[i];
    {
        const size_t src = (size_t)bh * (MM * EE) + oh * 32;
        for (int idx = tid; idx < MM * 32; idx += 128) {
            const int m = idx >> 5, o = idx & 31;
            s_Yr[idx] = g_Yr[src + (size_t)m * EE + o];
            s_Yi[idx] = g_Yi[src + (size_t)m * EE + o];
        }
    }
    __syncthreads();

    const int o0 = (tid & 3) * 8;     // local in half
    const int lg = tid >> 2;          // 0..31
    const int o_g = oh * 32 + o0;
    float* yb = y + ((size_t)b * LL * HH + h) * EE + o_g;
    const ull m1 = pack2(-1.0f, -1.0f);

    for (int pass = 0; pass < 2; ++pass) {
        const int lA = lc * 128 + pass * 64 + lg * 2;
        const int lB = lA + 1;

        ull aeA[4], aoA[4], aeB[4], aoB[4];
        #pragma unroll
        for (int k = 0; k < 4; ++k) { aeA[k] = 0; aoA[k] = 0; aeB[k] = 0; aoB[k] = 0; }

        int iA = 0, iB = 0;   // (m*lA)&2047, (m*lB)&2047 for even m
        #pragma unroll 4
        for (int m = 0; m < MM; m += 2) {
            {   // even m
                const ull cA = s_twd[iA], sA = s_twd[(iA + 512) & (LL - 1)];
                const ull cB = s_twd[iB], sB = s_twd[(iB + 512) & (LL - 1)];
                const ulonglong2 R0 = *(const ulonglong2*)&s_Yr[m * 32 + o0];
                const ulonglong2 R1 = *(const ulonglong2*)&s_Yr[m * 32 + o0 + 4];
                const ulonglong2 I0 = *(const ulonglong2*)&s_Yi[m * 32 + o0];
                const ulonglong2 I1 = *(const ulonglong2*)&s_Yi[m * 32 + o0 + 4];
                aeA[0] = fma2(R0.x, cA, aeA[0]); aeA[0] = fma2(I0.x, sA, aeA[0]);
                aeA[1] = fma2(R0.y, cA, aeA[1]); aeA[1] = fma2(I0.y, sA, aeA[1]);
                aeA[2] = fma2(R1.x, cA, aeA[2]); aeA[2] = fma2(I1.x, sA, aeA[2]);
                aeA[3] = fma2(R1.y, cA, aeA[3]); aeA[3] = fma2(I1.y, sA, aeA[3]);
                aeB[0] = fma2(R0.x, cB, aeB[0]); aeB[0] = fma2(I0.x, sB, aeB[0]);
                aeB[1] = fma2(R0.y, cB, aeB[1]); aeB[1] = fma2(I0.y, sB, aeB[1]);
                aeB[2] = fma2(R1.x, cB, aeB[2]); aeB[2] = fma2(I1.x, sB, aeB[2]);
                aeB[3] = fma2(R1.y, cB, aeB[3]); aeB[3] = fma2(I1.y, sB, aeB[3]);
            }
            {   // odd m+1
                const int jA = (iA + lA) & (LL - 1);
                const int jB = (iB + lB) & (LL - 1);
                const ull cA = s_twd[jA], sA = s_twd[(jA + 512) & (LL - 1)];
                const ull cB = s_twd[jB], sB = s_twd[(jB + 512) & (LL - 1)];
                const ulonglong2 R0 = *(const ulonglong2*)&s_Yr[(m + 1) * 32 + o0];
                const ulonglong2 R1 = *(const ulonglong2*)&s_Yr[(m + 1) * 32 + o0 + 4];
                const ulonglong2 I0 = *(const ulonglong2*)&s_Yi[(m + 1) * 32 + o0];
                const ulonglong2 I1 = *(const ulonglong2*)&s_Yi[(m + 1) * 32 + o0 + 4];
                aoA[0] = fma2(R0.x, cA, aoA[0]); aoA[0] = fma2(I0.x, sA, aoA[0]);
                aoA[1] = fma2(R0.y, cA, aoA[1]); aoA[1] = fma2(I0.y, sA, aoA[1]);
                aoA[2] = fma2(R1.x, cA, aoA[2]); aoA[2] = fma2(I1.x, sA, aoA[2]);
                aoA[3] = fma2(R1.y, cA, aoA[3]); aoA[3] = fma2(I1.y, sA, aoA[3]);
                aoB[0] = fma2(R0.x, cB, aoB[0]); aoB[0] = fma2(I0.x, sB, aoB[0]);
                aoB[1] = fma2(R0.y, cB, aoB[1]); aoB[1] = fma2(I0.y, sB, aoB[1]);
                aoB[2] = fma2(R1.x, cB, aoB[2]); aoB[2] = fma2(I1.x, sB, aoB[2]);
                aoB[3] = fma2(R1.y, cB, aoB[3]); aoB[3] = fma2(I1.y, sB, aoB[3]);
            }
            iA = (iA + 2 * lA) & (LL - 1);
            iB = (iB + 2 * lB) & (LL - 1);
        }

        // y_l = E+O ; y_{l+1024} = E-O   (packed f32x2 add / fused sub)
        {
            ulonglong2 lo0, lo1, hi0, hi1;
            lo0.x = add2(aeA[0], aoA[0]); lo0.y = add2(aeA[1], aoA[1]);
            lo1.x = add2(aeA[2], aoA[2]); lo1.y = add2(aeA[3], aoA[3]);
            hi0.x = fma2(aoA[0], m1, aeA[0]); hi0.y = fma2(aoA[1], m1, aeA[1]);
            hi1.x = fma2(aoA[2], m1, aeA[2]); hi1.y = fma2(aoA[3], m1, aeA[3]);
            *(ulonglong2*)&yb[(size_t)lA * (HH * EE)]               = lo0;
            *(ulonglong2*)&yb[(size_t)lA * (HH * EE) + 4]           = lo1;
            *(ulonglong2*)&yb[(size_t)(lA + LHALF) * (HH * EE)]     = hi0;
            *(ulonglong2*)&yb[(size_t)(lA + LHALF) * (HH * EE) + 4] = hi1;
        }
        {
            ulonglong2 lo0, lo1, hi0, hi1;
            lo0.x = add2(aeB[0], aoB[0]); lo0.y = add2(aeB[1], aoB[1]);
            lo1.x = add2(aeB[2], aoB[2]); lo1.y = add2(aeB[3], aoB[3]);
            hi0.x = fma2(aoB[0], m1, aeB[0]); hi0.y = fma2(aoB[1], m1, aeB[1]);
            hi1.x = fma2(aoB[2], m1, aeB[2]); hi1.y = fma2(aoB[3], m1, aeB[3]);
            *(ulonglong2*)&yb[(size_t)lB * (HH * EE)]               = lo0;
            *(ulonglong2*)&yb[(size_t)lB * (HH * EE) + 4]           = lo1;
            *(ulonglong2*)&yb[(size_t)(lB + LHALF) * (HH * EE)]     = hi0;
            *(ulonglong2*)&yb[(size_t)(lB + LHALF) * (HH * EE) + 4] = hi1;
        }
    }
}

extern "C" void kernel_launch(void* const* d_in, const int* in_sizes, int n_in,
                              void* d_out, int out_size) {
    (void)in_sizes; (void)n_in; (void)out_size;
    const float* x   = (const float*)d_in[0];
    const float* wre = (const float*)d_in[1];
    const float* wim = (const float*)d_in[2];
    float* y = (float*)d_out;

    k_tw<<<2, 1024>>>();
    k_trans<<<512, 256>>>(wre, wim);
    k_fwd<<<dim3(64, 8), 128>>>(x);
    k_mix<<<dim3(MM, HH), 128>>>();
    k_inv<<<dim3(64, 8, 2), 128>>>(y);
}